// round 14
// baseline (speedup 1.0000x reference)
#include <cuda_runtime.h>
#include <cuda_fp16.h>
#include <cstdint>
#include <cstddef>

// ---------------------------------------------------------------------------
// Problem constants
// ---------------------------------------------------------------------------
#define OUT_F 4096
#define IN_F  4096
#define M_TOTAL 8192           // 4 * 2048

// GEMM tiling: CTA tile 128x128, warp tile 64x64, 4 warps (2m x 2n),
// 2 CTAs per SM. A and B fragments BOTH double-buffered.
#define BM 128
#define BN 128
#define BK 64                  // halfs per stage k-slice = 128 bytes per row
#define STAGES 3
#define K_ITERS (IN_F / BK)    // 64
#define A_STAGE_BYTES (BM * BK * 2)            // 16384
#define B_STAGE_BYTES (BN * BK * 2)            // 16384
#define STAGE_BYTES (A_STAGE_BYTES + B_STAGE_BYTES)  // 32768
#define SMEM_TOTAL (STAGES * STAGE_BYTES)      // 98304 per CTA (x2 = 192KB/SM)

// ---------------------------------------------------------------------------
// Scratch (allocation-free rule: __device__ globals)
// ---------------------------------------------------------------------------
__device__ __align__(256) __half g_xh[(size_t)M_TOTAL * IN_F];  // x in fp16
__device__ __align__(256) __half g_wh[(size_t)OUT_F * IN_F];    // dequantized W in fp16

// ---------------------------------------------------------------------------
// Helpers
// ---------------------------------------------------------------------------
__device__ __forceinline__ uint32_t smem_u32(const void* p) {
    uint32_t a;
    asm("{ .reg .u64 t; cvta.to.shared.u64 t, %1; cvt.u32.u64 %0, t; }" : "=r"(a) : "l"(p));
    return a;
}

__device__ __forceinline__ uint32_t h2_bits(__half2 h) {
    return *reinterpret_cast<uint32_t*>(&h);
}

#define SWZ(off) ((off) ^ (((off) >> 3) & 0x70))

#define CP_ASYNC16(saddr, gptr) \
    asm volatile("cp.async.cg.shared.global [%0], [%1], 16;" :: "r"(saddr), "l"(gptr))
#define CP_ASYNC_COMMIT() asm volatile("cp.async.commit_group;" ::: "memory")
#define CP_ASYNC_WAIT(n)  asm volatile("cp.async.wait_group %0;" :: "n"(n) : "memory")

#define LDMATRIX_X4(r0, r1, r2, r3, addr)                                     \
    asm volatile("ldmatrix.sync.aligned.m8n8.x4.shared.b16 {%0,%1,%2,%3}, [%4];" \
                 : "=r"(r0), "=r"(r1), "=r"(r2), "=r"(r3) : "r"(addr))

#define MMA_16816(c, a0, a1, a2, a3, b0, b1)                                  \
    asm volatile("mma.sync.aligned.m16n8k16.row.col.f32.f16.f16.f32 "         \
                 "{%0,%1,%2,%3}, {%4,%5,%6,%7}, {%8,%9}, {%0,%1,%2,%3};"      \
                 : "+f"((c)[0]), "+f"((c)[1]), "+f"((c)[2]), "+f"((c)[3])     \
                 : "r"(a0), "r"(a1), "r"(a2), "r"(a3), "r"(b0), "r"(b1))

// Streaming store: C is write-once, never re-read -> don't pollute L2.
__device__ __forceinline__ void stcs_f2(float* p, float a, float b) {
    asm volatile("st.global.cs.v2.f32 [%0], {%1, %2};" :: "l"(p), "f"(a), "f"(b) : "memory");
}

// Loader chunk -> (swizzled smem offset, global element offset).
__device__ __forceinline__ void chunk_off(int c, uint32_t& soff, uint32_t& goff) {
    int row = c >> 3, c16 = c & 7;
    soff = SWZ((uint32_t)(row * 128 + c16 * 16));
    goff = (uint32_t)(row * IN_F + c16 * 8);
}

// ---------------------------------------------------------------------------
// Prep kernel 1: x (fp32) -> fp16
// ---------------------------------------------------------------------------
__global__ void __launch_bounds__(256) conv_x_kernel(const float* __restrict__ x) {
    size_t j = (size_t)blockIdx.x * blockDim.x + threadIdx.x;   // [0, 8388608)
    float4 v = reinterpret_cast<const float4*>(x)[j];
    uint2 o;
    o.x = h2_bits(__floats2half2_rn(v.x, v.y));
    o.y = h2_bits(__floats2half2_rn(v.z, v.w));
    reinterpret_cast<uint2*>(g_xh)[j] = o;
}

// ---------------------------------------------------------------------------
// Prep kernel 2: HQQ int4 dequant -> fp16
// ---------------------------------------------------------------------------
__global__ void __launch_bounds__(256) dequant_w_kernel(
    const int* __restrict__ Wq, const float* __restrict__ scale,
    const float* __restrict__ zero) {
    size_t j = (size_t)blockIdx.x * blockDim.x + threadIdx.x;   // [0, 2097152)
    int4 v = reinterpret_cast<const int4*>(Wq)[j];
    size_t g = j >> 3;
    float s = scale[g];
    float z = zero[g];
    uint4 o;
    o.x = h2_bits(__floats2half2_rn(((float)(v.x & 15) - z) * s,
                                    ((float)(v.x >> 4) - z) * s));
    o.y = h2_bits(__floats2half2_rn(((float)(v.y & 15) - z) * s,
                                    ((float)(v.y >> 4) - z) * s));
    o.z = h2_bits(__floats2half2_rn(((float)(v.z & 15) - z) * s,
                                    ((float)(v.z >> 4) - z) * s));
    o.w = h2_bits(__floats2half2_rn(((float)(v.w & 15) - z) * s,
                                    ((float)(v.w >> 4) - z) * s));
    reinterpret_cast<uint4*>(g_wh)[j] = o;
}

// ---------------------------------------------------------------------------
// GEMM: C[M_TOTAL, OUT_F] = g_xh @ g_wh^T (fp16 in, fp32 accum)
// 128 threads = 4 warps as 2(m) x 2(n); warp tile 64x64; 2 CTAs/SM.
// 3-stage cp.async pipeline; BOTH A and B fragments double-buffered.
// ---------------------------------------------------------------------------
__global__ void __launch_bounds__(128, 2) hqq_gemm_f16(float* __restrict__ C) {
    extern __shared__ __align__(1024) char smem[];
    const uint32_t sb = smem_u32(smem);

    const int tid = threadIdx.x;
    const int wid = tid >> 5;
    const int lid = tid & 31;
    const int warp_m = wid >> 1;       // 0..1
    const int warp_n = wid & 1;        // 0..1

    // Supertile mapping: groups of 16 m-tiles across all 32 n-tiles.
    const int NT = OUT_F / BN;         // 32
    const int GM = 16;
    int bid = blockIdx.x;
    int group = bid / (GM * NT);
    int rem = bid - group * (GM * NT);
    int m_tile = group * GM + (rem % GM);
    int n_tile = rem / GM;

    const __half* Ab = g_xh + (size_t)m_tile * BM * IN_F;
    const __half* Bb = g_wh + (size_t)n_tile * BN * IN_F;

    auto load_stage = [&](int stage, int kelem) {
        uint32_t sA = sb + stage * STAGE_BYTES;
        uint32_t sB = sA + A_STAGE_BYTES;
        const __half* gA = Ab + kelem;
        const __half* gB = Bb + kelem;
        uint32_t so, go;
        #pragma unroll
        for (int i = 0; i < 8; i++) {           // A: 1024 chunks, 8/thread
            chunk_off(tid + i * 128, so, go);
            CP_ASYNC16(sA + so, gA + go);
        }
        #pragma unroll
        for (int i = 0; i < 8; i++) {           // B: 1024 chunks, 8/thread
            chunk_off(tid + i * 128, so, go);
            CP_ASYNC16(sB + so, gB + go);
        }
    };

    // Prologue: stages 0..1
    #pragma unroll
    for (int s = 0; s < STAGES - 1; s++) {
        load_stage(s, s * BK);
        CP_ASYNC_COMMIT();
    }

    // Accumulators: 4 m-subtiles x 8 n-subtiles x 4 floats = 128 regs
    float acc[4][8][4];
    #pragma unroll
    for (int i = 0; i < 4; i++)
        #pragma unroll
        for (int j = 0; j < 8; j++)
            #pragma unroll
            for (int q = 0; q < 4; q++) acc[i][j][q] = 0.0f;

    // Per-thread ldmatrix address components
    const int a_row = warp_m * 64 + (lid & 15);
    const int a_kc  = (lid >> 4) * 8;
    const int b_row = warp_n * 64 + ((lid >> 4) ? 8 : 0) + (lid & 7);
    const int b_kc  = ((lid >> 3) & 1) * 8;

    auto ld_a = [&](uint32_t (&af)[4][4], uint32_t sA, int kk) {
        #pragma unroll
        for (int mt = 0; mt < 4; mt++) {
            uint32_t off = (uint32_t)(a_row + mt * 16) * 128
                         + (uint32_t)(kk * 16 + a_kc) * 2;
            LDMATRIX_X4(af[mt][0], af[mt][1], af[mt][2], af[mt][3], sA + SWZ(off));
        }
    };
    auto ld_b = [&](uint32_t (&bf)[4][4], uint32_t sB, int kk) {
        #pragma unroll
        for (int p = 0; p < 4; p++) {          // p covers n-subtiles {2p, 2p+1}
            uint32_t off = (uint32_t)(b_row + p * 16) * 128
                         + (uint32_t)(kk * 16 + b_kc) * 2;
            LDMATRIX_X4(bf[p][0], bf[p][1], bf[p][2], bf[p][3], sB + SWZ(off));
        }
    };

    // Fragments: A and B both double-buffered (32 + 32 regs)
    uint32_t afr[2][4][4], bfr[2][4][4];

    for (int k = 0; k < K_ITERS; k++) {
        CP_ASYNC_WAIT(STAGES - 2);   // stage k landed
        __syncthreads();             // all warps past iter k-1 compute

        const int s = k % STAGES;
        const uint32_t sA = sb + s * STAGE_BYTES;
        const uint32_t sB = sA + A_STAGE_BYTES;

        // Refill target: k-stage k+2 -> slot consumed at iter k-1
        const int kn = k + STAGES - 1;
        const bool do_load = (kn < K_ITERS);
        const uint32_t dA = sb + (kn % STAGES) * STAGE_BYTES;
        const uint32_t dB = dA + A_STAGE_BYTES;
        const __half* gA = Ab + (do_load ? kn * BK : 0);
        const __half* gB = Bb + (do_load ? kn * BK : 0);

        // Prime kk=0 fragments (A and B)
        ld_a(afr[0], sA, 0);
        ld_b(bfr[0], sB, 0);

        #pragma unroll
        for (int kk = 0; kk < BK / 16; kk++) {       // 4 k-steps of 16
            const int cur = kk & 1, nxt = cur ^ 1;
            // Prefetch kk+1 fragments before issuing kk's MMAs
            if (kk < BK / 16 - 1) {
                ld_a(afr[nxt], sA, kk + 1);
                ld_b(bfr[nxt], sB, kk + 1);
            }
            // Drip 4 cp.async per kk step (2 A + 2 B), 16 total per iter
            if (do_load) {
                uint32_t so, go;
                chunk_off(tid + (kk * 2) * 128, so, go);
                CP_ASYNC16(dA + so, gA + go);
                CP_ASYNC16(dB + so, gB + go);
                chunk_off(tid + (kk * 2 + 1) * 128, so, go);
                CP_ASYNC16(dA + so, gA + go);
                CP_ASYNC16(dB + so, gB + go);
            }
            #pragma unroll
            for (int mt = 0; mt < 4; mt++)
                #pragma unroll
                for (int nt = 0; nt < 8; nt++)
                    MMA_16816(acc[mt][nt],
                              afr[cur][mt][0], afr[cur][mt][1],
                              afr[cur][mt][2], afr[cur][mt][3],
                              bfr[cur][nt >> 1][(nt & 1) * 2],
                              bfr[cur][nt >> 1][(nt & 1) * 2 + 1]);
        }
        CP_ASYNC_COMMIT();           // one group per iter (possibly empty)
    }

    // Epilogue: fragment layout -> global fp32, streaming stores
    const int m0 = m_tile * BM + warp_m * 64 + (lid >> 2);
    const int n0 = n_tile * BN + warp_n * 64 + (lid & 3) * 2;
    #pragma unroll
    for (int mt = 0; mt < 4; mt++) {
        #pragma unroll
        for (int nt = 0; nt < 8; nt++) {
            float* p0 = C + (size_t)(m0 + mt * 16) * OUT_F + (n0 + nt * 8);
            float* p1 = p0 + 8 * OUT_F;
            stcs_f2(p0, acc[mt][nt][0], acc[mt][nt][1]);
            stcs_f2(p1, acc[mt][nt][2], acc[mt][nt][3]);
        }
    }
}

// ---------------------------------------------------------------------------
// Launch
// ---------------------------------------------------------------------------
extern "C" void kernel_launch(void* const* d_in, const int* in_sizes, int n_in,
                              void* d_out, int out_size) {
    const float* x     = (const float*)d_in[0];
    const int*   Wq    = (const int*)d_in[1];
    const float* scale = (const float*)d_in[2];
    const float* zero  = (const float*)d_in[3];
    float* out = (float*)d_out;

    cudaFuncSetAttribute(hqq_gemm_f16, cudaFuncAttributeMaxDynamicSharedMemorySize, SMEM_TOTAL);

    conv_x_kernel<<<8388608 / 256, 256>>>(x);
    dequant_w_kernel<<<2097152 / 256, 256>>>(Wq, scale, zero);

    int grid = (M_TOTAL / BM) * (OUT_F / BN);   // 2048
    hqq_gemm_f16<<<grid, 128, SMEM_TOTAL>>>(out);
}

// round 15
// speedup vs baseline: 1.0712x; 1.0712x over previous
#include <cuda_runtime.h>
#include <cuda_fp16.h>
#include <cstdint>
#include <cstddef>

// ---------------------------------------------------------------------------
// Problem constants
// ---------------------------------------------------------------------------
#define OUT_F 4096
#define IN_F  4096
#define M_TOTAL 8192           // 4 * 2048

// GEMM tiling: CTA tile 128x128, warp tile 64x64, 4 warps (2m x 2n),
// 2 CTAs per SM. B fragments double-buffered, A single-buffered (R12 config).
#define BM 128
#define BN 128
#define BK 64                  // halfs per stage k-slice = 128 bytes per row
#define STAGES 3
#define K_ITERS (IN_F / BK)    // 64
#define A_STAGE_BYTES (BM * BK * 2)            // 16384
#define B_STAGE_BYTES (BN * BK * 2)            // 16384
#define STAGE_BYTES (A_STAGE_BYTES + B_STAGE_BYTES)  // 32768
#define SMEM_TOTAL (STAGES * STAGE_BYTES)      // 98304 per CTA (x2 = 192KB/SM)

// Prep grid split: x-convert blocks then W-dequant blocks in one launch
#define X_BLOCKS 32768         // 8388608 float4 chunks / 256
#define W_BLOCKS 8192          // 2097152 int4 chunks / 256

// ---------------------------------------------------------------------------
// Scratch (allocation-free rule: __device__ globals)
// ---------------------------------------------------------------------------
__device__ __align__(256) __half g_xh[(size_t)M_TOTAL * IN_F];  // x in fp16
__device__ __align__(256) __half g_wh[(size_t)OUT_F * IN_F];    // dequantized W in fp16

// ---------------------------------------------------------------------------
// Helpers
// ---------------------------------------------------------------------------
__device__ __forceinline__ uint32_t smem_u32(const void* p) {
    uint32_t a;
    asm("{ .reg .u64 t; cvta.to.shared.u64 t, %1; cvt.u32.u64 %0, t; }" : "=r"(a) : "l"(p));
    return a;
}

__device__ __forceinline__ uint32_t h2_bits(__half2 h) {
    return *reinterpret_cast<uint32_t*>(&h);
}

#define SWZ(off) ((off) ^ (((off) >> 3) & 0x70))

#define CP_ASYNC16(saddr, gptr) \
    asm volatile("cp.async.cg.shared.global [%0], [%1], 16;" :: "r"(saddr), "l"(gptr))
#define CP_ASYNC_COMMIT() asm volatile("cp.async.commit_group;" ::: "memory")
#define CP_ASYNC_WAIT(n)  asm volatile("cp.async.wait_group %0;" :: "n"(n) : "memory")

#define LDMATRIX_X4(r0, r1, r2, r3, addr)                                     \
    asm volatile("ldmatrix.sync.aligned.m8n8.x4.shared.b16 {%0,%1,%2,%3}, [%4];" \
                 : "=r"(r0), "=r"(r1), "=r"(r2), "=r"(r3) : "r"(addr))

#define MMA_16816(c, a0, a1, a2, a3, b0, b1)                                  \
    asm volatile("mma.sync.aligned.m16n8k16.row.col.f32.f16.f16.f32 "         \
                 "{%0,%1,%2,%3}, {%4,%5,%6,%7}, {%8,%9}, {%0,%1,%2,%3};"      \
                 : "+f"((c)[0]), "+f"((c)[1]), "+f"((c)[2]), "+f"((c)[3])     \
                 : "r"(a0), "r"(a1), "r"(a2), "r"(a3), "r"(b0), "r"(b1))

// Streaming store: C is write-once, never re-read -> don't pollute L2.
__device__ __forceinline__ void stcs_f2(float* p, float a, float b) {
    asm volatile("st.global.cs.v2.f32 [%0], {%1, %2};" :: "l"(p), "f"(a), "f"(b) : "memory");
}

// Loader chunk -> (swizzled smem offset, global element offset).
__device__ __forceinline__ void chunk_off(int c, uint32_t& soff, uint32_t& goff) {
    int row = c >> 3, c16 = c & 7;
    soff = SWZ((uint32_t)(row * 128 + c16 * 16));
    goff = (uint32_t)(row * IN_F + c16 * 8);
}

// ---------------------------------------------------------------------------
// Merged prep kernel: first X_BLOCKS blocks convert x (fp32 -> fp16),
// remaining W_BLOCKS blocks dequantize HQQ int4 -> fp16. One launch lets the
// two memory-bound phases share the chip and drops one launch boundary.
// ---------------------------------------------------------------------------
__global__ void __launch_bounds__(256) prep_kernel(
    const float* __restrict__ x, const int* __restrict__ Wq,
    const float* __restrict__ scale, const float* __restrict__ zero) {
    if (blockIdx.x < X_BLOCKS) {
        size_t j = (size_t)blockIdx.x * 256 + threadIdx.x;      // [0, 8388608)
        float4 v = reinterpret_cast<const float4*>(x)[j];
        uint2 o;
        o.x = h2_bits(__floats2half2_rn(v.x, v.y));
        o.y = h2_bits(__floats2half2_rn(v.z, v.w));
        reinterpret_cast<uint2*>(g_xh)[j] = o;
    } else {
        size_t j = (size_t)(blockIdx.x - X_BLOCKS) * 256 + threadIdx.x;  // [0, 2097152)
        int4 v = reinterpret_cast<const int4*>(Wq)[j];
        size_t g = j >> 3;
        float s = scale[g];
        float z = zero[g];
        uint4 o;
        o.x = h2_bits(__floats2half2_rn(((float)(v.x & 15) - z) * s,
                                        ((float)(v.x >> 4) - z) * s));
        o.y = h2_bits(__floats2half2_rn(((float)(v.y & 15) - z) * s,
                                        ((float)(v.y >> 4) - z) * s));
        o.z = h2_bits(__floats2half2_rn(((float)(v.z & 15) - z) * s,
                                        ((float)(v.z >> 4) - z) * s));
        o.w = h2_bits(__floats2half2_rn(((float)(v.w & 15) - z) * s,
                                        ((float)(v.w >> 4) - z) * s));
        reinterpret_cast<uint4*>(g_wh)[j] = o;
    }
}

// ---------------------------------------------------------------------------
// GEMM: C[M_TOTAL, OUT_F] = g_xh @ g_wh^T (fp16 in, fp32 accum)
// 128 threads = 4 warps as 2(m) x 2(n); warp tile 64x64; 2 CTAs/SM.
// 3-stage cp.async pipeline; B double-buffered fragments, A single-buffered.
// ---------------------------------------------------------------------------
__global__ void __launch_bounds__(128, 2) hqq_gemm_f16(float* __restrict__ C) {
    extern __shared__ __align__(1024) char smem[];
    const uint32_t sb = smem_u32(smem);

    const int tid = threadIdx.x;
    const int wid = tid >> 5;
    const int lid = tid & 31;
    const int warp_m = wid >> 1;       // 0..1
    const int warp_n = wid & 1;        // 0..1

    // Supertile mapping: groups of 32 m-tiles across all 32 n-tiles.
    // Group working set: A 33.5MB + B 34MB < L2; halves B DRAM re-reads vs GM=16.
    const int NT = OUT_F / BN;         // 32
    const int GM = 32;
    int bid = blockIdx.x;
    int group = bid / (GM * NT);
    int rem = bid - group * (GM * NT);
    int m_tile = group * GM + (rem % GM);
    int n_tile = rem / GM;

    const __half* Ab = g_xh + (size_t)m_tile * BM * IN_F;
    const __half* Bb = g_wh + (size_t)n_tile * BN * IN_F;

    auto load_stage = [&](int stage, int kelem) {
        uint32_t sA = sb + stage * STAGE_BYTES;
        uint32_t sB = sA + A_STAGE_BYTES;
        const __half* gA = Ab + kelem;
        const __half* gB = Bb + kelem;
        uint32_t so, go;
        #pragma unroll
        for (int i = 0; i < 8; i++) {           // A: 1024 chunks, 8/thread
            chunk_off(tid + i * 128, so, go);
            CP_ASYNC16(sA + so, gA + go);
        }
        #pragma unroll
        for (int i = 0; i < 8; i++) {           // B: 1024 chunks, 8/thread
            chunk_off(tid + i * 128, so, go);
            CP_ASYNC16(sB + so, gB + go);
        }
    };

    // Prologue: stages 0..1
    #pragma unroll
    for (int s = 0; s < STAGES - 1; s++) {
        load_stage(s, s * BK);
        CP_ASYNC_COMMIT();
    }

    // Accumulators: 4 m-subtiles x 8 n-subtiles x 4 floats = 128 regs
    float acc[4][8][4];
    #pragma unroll
    for (int i = 0; i < 4; i++)
        #pragma unroll
        for (int j = 0; j < 8; j++)
            #pragma unroll
            for (int q = 0; q < 4; q++) acc[i][j][q] = 0.0f;

    // Per-thread ldmatrix address components
    const int a_row = warp_m * 64 + (lid & 15);
    const int a_kc  = (lid >> 4) * 8;
    const int b_row = warp_n * 64 + ((lid >> 4) ? 8 : 0) + (lid & 7);
    const int b_kc  = ((lid >> 3) & 1) * 8;

    auto ld_a = [&](uint32_t (&af)[4][4], uint32_t sA, int kk) {
        #pragma unroll
        for (int mt = 0; mt < 4; mt++) {
            uint32_t off = (uint32_t)(a_row + mt * 16) * 128
                         + (uint32_t)(kk * 16 + a_kc) * 2;
            LDMATRIX_X4(af[mt][0], af[mt][1], af[mt][2], af[mt][3], sA + SWZ(off));
        }
    };
    auto ld_b = [&](uint32_t (&bf)[4][4], uint32_t sB, int kk) {
        #pragma unroll
        for (int p = 0; p < 4; p++) {          // p covers n-subtiles {2p, 2p+1}
            uint32_t off = (uint32_t)(b_row + p * 16) * 128
                         + (uint32_t)(kk * 16 + b_kc) * 2;
            LDMATRIX_X4(bf[p][0], bf[p][1], bf[p][2], bf[p][3], sB + SWZ(off));
        }
    };

    // Fragments: A single-buffered (16 regs), B double-buffered (32 regs)
    uint32_t afr[4][4], bfr[2][4][4];

    for (int k = 0; k < K_ITERS; k++) {
        CP_ASYNC_WAIT(STAGES - 2);   // stage k landed
        __syncthreads();             // all warps past iter k-1 compute

        const int s = k % STAGES;
        const uint32_t sA = sb + s * STAGE_BYTES;
        const uint32_t sB = sA + A_STAGE_BYTES;

        // Refill target: k-stage k+2 -> slot consumed at iter k-1
        const int kn = k + STAGES - 1;
        const bool do_load = (kn < K_ITERS);
        const uint32_t dA = sb + (kn % STAGES) * STAGE_BYTES;
        const uint32_t dB = dA + A_STAGE_BYTES;
        const __half* gA = Ab + (do_load ? kn * BK : 0);
        const __half* gB = Bb + (do_load ? kn * BK : 0);

        // Prime B kk=0 fragments
        ld_b(bfr[0], sB, 0);

        #pragma unroll
        for (int kk = 0; kk < BK / 16; kk++) {       // 4 k-steps of 16
            const int cur = kk & 1, nxt = cur ^ 1;
            ld_a(afr, sA, kk);                        // single-buffered A
            if (kk < BK / 16 - 1) ld_b(bfr[nxt], sB, kk + 1);
            // Drip 4 cp.async per kk step (2 A + 2 B), 16 total per iter
            if (do_load) {
                uint32_t so, go;
                chunk_off(tid + (kk * 2) * 128, so, go);
                CP_ASYNC16(dA + so, gA + go);
                CP_ASYNC16(dB + so, gB + go);
                chunk_off(tid + (kk * 2 + 1) * 128, so, go);
                CP_ASYNC16(dA + so, gA + go);
                CP_ASYNC16(dB + so, gB + go);
            }
            #pragma unroll
            for (int mt = 0; mt < 4; mt++)
                #pragma unroll
                for (int nt = 0; nt < 8; nt++)
                    MMA_16816(acc[mt][nt],
                              afr[mt][0], afr[mt][1], afr[mt][2], afr[mt][3],
                              bfr[cur][nt >> 1][(nt & 1) * 2],
                              bfr[cur][nt >> 1][(nt & 1) * 2 + 1]);
        }
        CP_ASYNC_COMMIT();           // one group per iter (possibly empty)
    }

    // Epilogue: fragment layout -> global fp32, streaming stores
    const int m0 = m_tile * BM + warp_m * 64 + (lid >> 2);
    const int n0 = n_tile * BN + warp_n * 64 + (lid & 3) * 2;
    #pragma unroll
    for (int mt = 0; mt < 4; mt++) {
        #pragma unroll
        for (int nt = 0; nt < 8; nt++) {
            float* p0 = C + (size_t)(m0 + mt * 16) * OUT_F + (n0 + nt * 8);
            float* p1 = p0 + 8 * OUT_F;
            stcs_f2(p0, acc[mt][nt][0], acc[mt][nt][1]);
            stcs_f2(p1, acc[mt][nt][2], acc[mt][nt][3]);
        }
    }
}

// ---------------------------------------------------------------------------
// Launch
// ---------------------------------------------------------------------------
extern "C" void kernel_launch(void* const* d_in, const int* in_sizes, int n_in,
                              void* d_out, int out_size) {
    const float* x     = (const float*)d_in[0];
    const int*   Wq    = (const int*)d_in[1];
    const float* scale = (const float*)d_in[2];
    const float* zero  = (const float*)d_in[3];
    float* out = (float*)d_out;

    cudaFuncSetAttribute(hqq_gemm_f16, cudaFuncAttributeMaxDynamicSharedMemorySize, SMEM_TOTAL);

    prep_kernel<<<X_BLOCKS + W_BLOCKS, 256>>>(x, Wq, scale, zero);

    int grid = (M_TOTAL / BM) * (OUT_F / BN);   // 2048
    hqq_gemm_f16<<<grid, 128, SMEM_TOTAL>>>(out);
}